// round 10
// baseline (speedup 1.0000x reference)
#include <cuda_runtime.h>

#define N_NODES  100000
#define N_EDGES  1600000
#define N_GRAPHS 512
#define F_IN     256
#define HID      64
#define NB_SCAN  ((N_NODES + 255) / 256)   // 391 scan blocks

typedef unsigned long long ull;

// ---------------- scratch (static device globals; no runtime alloc) ----------------
// NOTE: g_indeg relies on zero-init at module load; k_scatter re-zeroes it each run.
__device__ float2 g_h1[(size_t)N_NODES * 32];   // x @ W1, as 32 float2 per node
__device__ int    g_indeg[N_NODES];
__device__ float  g_dinv[N_NODES];
__device__ int    g_off[N_NODES + 1];
__device__ int    g_cursor[N_NODES];
__device__ int    g_bsum[NB_SCAN];
__device__ int2   g_edge[N_EDGES];              // (src, norm-as-bits), bucketed by dst
__device__ float2 g_msg2[N_NODES];              // relu(agg1) @ W2

// ---------------- f32x2 helpers ----------------
__device__ __forceinline__ ull pack2(float v) {
    ull r;
    asm("mov.b64 %0, {%1, %1};" : "=l"(r) : "f"(v));
    return r;
}
__device__ __forceinline__ ull fma2(ull a, ull b, ull c) {
    ull d;
    asm("fma.rn.f32x2 %0, %1, %2, %3;" : "=l"(d) : "l"(a), "l"(b), "l"(c));
    return d;
}

// ---------------- K1: in-degree histogram over dst ----------------
__global__ void k_hist(const int* __restrict__ ei) {
    int e = blockIdx.x * blockDim.x + threadIdx.x;
    if (e < N_EDGES) atomicAdd(&g_indeg[ei[N_EDGES + e]], 1);
}

// ---------------- scan helpers ----------------
__device__ __forceinline__ int warp_incl_scan(int v) {
#pragma unroll
    for (int o = 1; o < 32; o <<= 1) {
        int n = __shfl_up_sync(0xffffffffu, v, o);
        if ((threadIdx.x & 31) >= o) v += n;
    }
    return v;
}

// K2a: per-block exclusive scan of indeg + fused dinv = rsqrt(indeg+1)
__global__ void k_scan1(void) {
    __shared__ int wsum[8];
    __shared__ int woff[8];
    int i = blockIdx.x * 256 + threadIdx.x;
    int v = (i < N_NODES) ? g_indeg[i] : 0;
    if (i < N_NODES) g_dinv[i] = rsqrtf((float)(v + 1));
    int incl = warp_incl_scan(v);
    int lane = threadIdx.x & 31, wid = threadIdx.x >> 5;
    if (lane == 31) wsum[wid] = incl;
    __syncthreads();
    if (threadIdx.x == 0) {
        int r = 0;
#pragma unroll
        for (int w = 0; w < 8; ++w) { woff[w] = r; r += wsum[w]; }
        g_bsum[blockIdx.x] = r;
    }
    __syncthreads();
    if (i < N_NODES) g_off[i] = incl - v + woff[wid];
}

// K2b: fused block-sum prefix + finalize offsets
__global__ void k_scan3(void) {
    __shared__ int red[256];
    int t = threadIdx.x;
    int acc = 0;
    for (int j = t; j < NB_SCAN; j += 256)
        if (j < blockIdx.x) acc += g_bsum[j];
    red[t] = acc;
    __syncthreads();
    for (int o = 128; o > 0; o >>= 1) {
        if (t < o) red[t] += red[t + o];
        __syncthreads();
    }
    int base = red[0];
    int i = blockIdx.x * 256 + t;
    if (i < N_NODES) {
        int o = g_off[i] + base;
        g_off[i] = o;
        g_cursor[i] = o;
    }
    if (i == 0) g_off[N_NODES] = N_EDGES;
}

// ---------------- K3: scatter edges into dst buckets; re-zero indeg for next run ----
__global__ void k_scatter(const int* __restrict__ ei) {
    int e = blockIdx.x * blockDim.x + threadIdx.x;
    if (e < N_NODES) g_indeg[e] = 0;   // indeg is dead after scan1; reset for next replay
    if (e >= N_EDGES) return;
    int s = ei[e];
    int d = ei[N_EDGES + e];
    float norm = g_dinv[s] * g_dinv[d];
    int pos = atomicAdd(&g_cursor[d], 1);
    g_edge[pos] = make_int2(s, __float_as_int(norm));
}

// ---------------- K4: GEMM1  h1 = x @ W1  (f32x2, K-chunked, x read once) ----------
__global__ void __launch_bounds__(256) k_gemm1(const float* __restrict__ x,
                                               const float* __restrict__ W1) {
    __shared__ ull Wp[128 * 32];   // 32KB: rows k (128), 32 column-pairs each
    int node = blockIdx.x * 256 + threadIdx.x;

    ull acc[32];
#pragma unroll
    for (int j = 0; j < 32; ++j) acc[j] = 0ull;

#pragma unroll
    for (int chunk = 0; chunk < 2; ++chunk) {
        __syncthreads();   // protect previous chunk's Wp
        {
            const ulonglong2* src = reinterpret_cast<const ulonglong2*>(W1) + chunk * 2048;
            ulonglong2* dst = reinterpret_cast<ulonglong2*>(Wp);
            for (int i = threadIdx.x; i < 2048; i += 256) dst[i] = src[i];
        }
        __syncthreads();

        if (node < N_NODES) {
            const float4* xrow =
                reinterpret_cast<const float4*>(x + (size_t)node * F_IN + chunk * 128);
            for (int k4 = 0; k4 < 32; ++k4) {
                float4 xv = xrow[k4];
                float xa[4] = {xv.x, xv.y, xv.z, xv.w};
#pragma unroll
                for (int kk = 0; kk < 4; ++kk) {
                    ull xs2 = pack2(xa[kk]);
                    const ull* wr = Wp + (k4 * 4 + kk) * 32;
#pragma unroll
                    for (int j = 0; j < 32; ++j) acc[j] = fma2(xs2, wr[j], acc[j]);
                }
            }
        }
    }

    if (node < N_NODES) {
        ulonglong2* o = reinterpret_cast<ulonglong2*>(g_h1 + (size_t)node * 32);
#pragma unroll
        for (int j = 0; j < 16; ++j) o[j] = make_ulonglong2(acc[2 * j], acc[2 * j + 1]);
    }
}

// ---------------- K5: fused gather1 + bias + relu + layer2 GEMV ----------------
// One warp per node, split into two half-warps over edges.
// Lane: hw = lane>>4 (edge-interleave half), c = lane&15 (owns cols 4c..4c+3).
// Each half processes alternating edges with x2 unroll -> 4 row loads in flight/warp.
__global__ void __launch_bounds__(256) k_gather1(const float* __restrict__ b1,
                                                 const float* __restrict__ W2) {
    __shared__ float W2s[HID * 2];
    if (threadIdx.x < HID * 2) W2s[threadIdx.x] = W2[threadIdx.x];
    __syncthreads();

    int node = blockIdx.x * 8 + (threadIdx.x >> 5);
    if (node >= N_NODES) return;
    int lane = threadIdx.x & 31;
    int hw = lane >> 4;
    int c = lane & 15;

    const float4* h1 = reinterpret_cast<const float4*>(g_h1);  // 16 float4 per node row

    float4 acc = make_float4(0.0f, 0.0f, 0.0f, 0.0f);
    if (hw == 0) {  // self loop counted once (half 0 only)
        float dn = g_dinv[node];
        float d2 = dn * dn;
        float4 hv = h1[(size_t)node * 16 + c];
        acc = make_float4(hv.x * d2, hv.y * d2, hv.z * d2, hv.w * d2);
    }

    int beg = g_off[node], end = g_off[node + 1];
    int e = beg + hw;
    for (; e + 2 < end; e += 4) {       // this half handles e and e+2
        int2 e0 = g_edge[e];
        int2 e1 = g_edge[e + 2];
        float4 v0 = h1[(size_t)e0.x * 16 + c];
        float4 v1 = h1[(size_t)e1.x * 16 + c];
        float n0 = __int_as_float(e0.y);
        float n1 = __int_as_float(e1.y);
        acc.x = fmaf(v0.x, n0, acc.x);
        acc.y = fmaf(v0.y, n0, acc.y);
        acc.z = fmaf(v0.z, n0, acc.z);
        acc.w = fmaf(v0.w, n0, acc.w);
        acc.x = fmaf(v1.x, n1, acc.x);
        acc.y = fmaf(v1.y, n1, acc.y);
        acc.z = fmaf(v1.z, n1, acc.z);
        acc.w = fmaf(v1.w, n1, acc.w);
    }
    if (e < end) {
        int2 e0 = g_edge[e];
        float4 v0 = h1[(size_t)e0.x * 16 + c];
        float n0 = __int_as_float(e0.y);
        acc.x = fmaf(v0.x, n0, acc.x);
        acc.y = fmaf(v0.y, n0, acc.y);
        acc.z = fmaf(v0.z, n0, acc.z);
        acc.w = fmaf(v0.w, n0, acc.w);
    }

    // combine the two halves (lane i <-> lane i+16 hold the same columns)
    acc.x += __shfl_xor_sync(0xffffffffu, acc.x, 16);
    acc.y += __shfl_xor_sync(0xffffffffu, acc.y, 16);
    acc.z += __shfl_xor_sync(0xffffffffu, acc.z, 16);
    acc.w += __shfl_xor_sync(0xffffffffu, acc.w, 16);

    // bias + relu + layer-2 GEMV partials (cols 4c..4c+3)
    float4 bb = reinterpret_cast<const float4*>(b1)[c];
    float r0 = fmaxf(acc.x + bb.x, 0.0f);
    float r1 = fmaxf(acc.y + bb.y, 0.0f);
    float r2 = fmaxf(acc.z + bb.z, 0.0f);
    float r3 = fmaxf(acc.w + bb.w, 0.0f);
    float a0 = r0 * W2s[8 * c + 0] + r1 * W2s[8 * c + 2] +
               r2 * W2s[8 * c + 4] + r3 * W2s[8 * c + 6];
    float a1 = r0 * W2s[8 * c + 1] + r1 * W2s[8 * c + 3] +
               r2 * W2s[8 * c + 5] + r3 * W2s[8 * c + 7];
#pragma unroll
    for (int o = 8; o > 0; o >>= 1) {   // reduce within each 16-lane half
        a0 += __shfl_down_sync(0xffffffffu, a0, o, 16);
        a1 += __shfl_down_sync(0xffffffffu, a1, o, 16);
    }
    if (lane == 0) g_msg2[node] = make_float2(a0, a1);
}

// ---------------- K6: fused gather2 + mean-pool (one block per graph) ---------------
__device__ __forceinline__ int lower_bound_i(const int* __restrict__ a, int key) {
    int lo = 0, hi = N_NODES;
    while (lo < hi) {
        int mid = (lo + hi) >> 1;
        if (a[mid] < key) lo = mid + 1; else hi = mid;
    }
    return lo;
}

__global__ void __launch_bounds__(256) k_pool(const int* __restrict__ batch,
                                              const float* __restrict__ b2,
                                              float* __restrict__ out) {
    __shared__ float sx[256], sy[256];
    int g = blockIdx.x;
    int lo = lower_bound_i(batch, g);
    int hi = lower_bound_i(batch, g + 1);
    float bx = b2[0], by = b2[1];
    float ax = 0.0f, ay = 0.0f;
    for (int i = lo + threadIdx.x; i < hi; i += 256) {
        float dn = g_dinv[i];
        float2 m = g_msg2[i];
        float d2 = dn * dn;
        float vx = bx + m.x * d2;
        float vy = by + m.y * d2;
        int beg = g_off[i], end = g_off[i + 1];
        int e = beg;
        for (; e + 2 <= end; e += 2) {
            int2 e0 = g_edge[e];
            int2 e1 = g_edge[e + 1];
            float2 v0 = g_msg2[e0.x];
            float2 v1 = g_msg2[e1.x];
            float n0 = __int_as_float(e0.y);
            float n1 = __int_as_float(e1.y);
            vx = fmaf(v0.x, n0, vx);
            vy = fmaf(v0.y, n0, vy);
            vx = fmaf(v1.x, n1, vx);
            vy = fmaf(v1.y, n1, vy);
        }
        if (e < end) {
            int2 e0 = g_edge[e];
            float n0 = __int_as_float(e0.y);
            float2 v0 = g_msg2[e0.x];
            vx = fmaf(v0.x, n0, vx);
            vy = fmaf(v0.y, n0, vy);
        }
        ax += vx;
        ay += vy;
    }
    sx[threadIdx.x] = ax;
    sy[threadIdx.x] = ay;
    __syncthreads();
    for (int o = 128; o > 0; o >>= 1) {
        if (threadIdx.x < o) {
            sx[threadIdx.x] += sx[threadIdx.x + o];
            sy[threadIdx.x] += sy[threadIdx.x + o];
        }
        __syncthreads();
    }
    if (threadIdx.x == 0) {
        float c = fmaxf((float)(hi - lo), 1.0f);
        out[g * 2 + 0] = sx[0] / c;
        out[g * 2 + 1] = sy[0] / c;
    }
}

// ---------------- launch ----------------
// Capture order chosen so k_gemm1 is the 4th kernel launch (ncu -s 5 profiles it).
extern "C" void kernel_launch(void* const* d_in, const int* in_sizes, int n_in,
                              void* d_out, int out_size) {
    const float* x     = (const float*)d_in[0];
    const int*   ei    = (const int*)d_in[1];    // int32
    const int*   batch = (const int*)d_in[2];    // int32
    const float* W1    = (const float*)d_in[3];
    const float* b1    = (const float*)d_in[4];
    const float* W2    = (const float*)d_in[5];
    const float* b2    = (const float*)d_in[6];
    float*       out   = (float*)d_out;

    cudaStream_t s2;
    cudaEvent_t evFork, evJoin;
    cudaStreamCreateWithFlags(&s2, cudaStreamNonBlocking);
    cudaEventCreateWithFlags(&evFork, cudaEventDisableTiming);
    cudaEventCreateWithFlags(&evJoin, cudaEventDisableTiming);

    // Fork point (before any main-stream work).
    cudaEventRecord(evFork, 0);
    cudaStreamWaitEvent(s2, evFork, 0);

    // Main stream: CSR build chain (indeg pre-zeroed by previous run's scatter).
    k_hist<<<(N_EDGES + 255) / 256, 256>>>(ei);        // launch 1
    k_scan1<<<NB_SCAN, 256>>>();                       // launch 2
    k_scan3<<<NB_SCAN, 256>>>();                       // launch 3

    // Side stream: dense projection (depends only on fork event).
    k_gemm1<<<(N_NODES + 255) / 256, 256, 0, s2>>>(x, W1);  // launch 4 (profiled)
    cudaEventRecord(evJoin, s2);

    k_scatter<<<(N_EDGES + 255) / 256, 256>>>(ei);     // launch 5

    // Join: gather1 needs both h1 and the CSR.
    cudaStreamWaitEvent(0, evJoin, 0);
    k_gather1<<<(N_NODES + 7) / 8, 256>>>(b1, W2);     // launch 6
    k_pool<<<N_GRAPHS, 256>>>(batch, b2, out);         // launch 7
}

// round 11
// speedup vs baseline: 1.5653x; 1.5653x over previous
#include <cuda_runtime.h>

#define N_NODES  100000
#define N_EDGES  1600000
#define N_GRAPHS 512
#define F_IN     256
#define HID      64
#define NB_SCAN  ((N_NODES + 255) / 256)   // 391 scan blocks

typedef unsigned long long ull;

// ---------------- scratch (static device globals; no runtime alloc) ----------------
// NOTE: g_indeg relies on zero-init at module load; k_scatter re-zeroes it each run.
__device__ float2 g_h1[(size_t)N_NODES * 32];   // x @ W1, as 32 float2 per node
__device__ int    g_indeg[N_NODES];
__device__ float  g_dinv[N_NODES];
__device__ int    g_off[N_NODES + 1];
__device__ int    g_cursor[N_NODES];
__device__ int    g_bsum[NB_SCAN];
__device__ int2   g_edge[N_EDGES];              // (src, norm-as-bits), bucketed by dst
__device__ float2 g_msg2[N_NODES];              // relu(agg1) @ W2

// ---------------- f32x2 helpers ----------------
__device__ __forceinline__ ull pack2(float v) {
    ull r;
    asm("mov.b64 %0, {%1, %1};" : "=l"(r) : "f"(v));
    return r;
}
__device__ __forceinline__ ull fma2(ull a, ull b, ull c) {
    ull d;
    asm("fma.rn.f32x2 %0, %1, %2, %3;" : "=l"(d) : "l"(a), "l"(b), "l"(c));
    return d;
}

// ---------------- K1: in-degree histogram over dst ----------------
__global__ void k_hist(const int* __restrict__ ei) {
    int e = blockIdx.x * blockDim.x + threadIdx.x;
    if (e < N_EDGES) atomicAdd(&g_indeg[ei[N_EDGES + e]], 1);
}

// ---------------- scan helpers ----------------
__device__ __forceinline__ int warp_incl_scan(int v) {
#pragma unroll
    for (int o = 1; o < 32; o <<= 1) {
        int n = __shfl_up_sync(0xffffffffu, v, o);
        if ((threadIdx.x & 31) >= o) v += n;
    }
    return v;
}

// K2a: per-block exclusive scan of indeg + fused dinv = rsqrt(indeg+1)
__global__ void k_scan1(void) {
    __shared__ int wsum[8];
    __shared__ int woff[8];
    int i = blockIdx.x * 256 + threadIdx.x;
    int v = (i < N_NODES) ? g_indeg[i] : 0;
    if (i < N_NODES) g_dinv[i] = rsqrtf((float)(v + 1));
    int incl = warp_incl_scan(v);
    int lane = threadIdx.x & 31, wid = threadIdx.x >> 5;
    if (lane == 31) wsum[wid] = incl;
    __syncthreads();
    if (threadIdx.x == 0) {
        int r = 0;
#pragma unroll
        for (int w = 0; w < 8; ++w) { woff[w] = r; r += wsum[w]; }
        g_bsum[blockIdx.x] = r;
    }
    __syncthreads();
    if (i < N_NODES) g_off[i] = incl - v + woff[wid];
}

// K2b: fused block-sum prefix + finalize offsets
__global__ void k_scan3(void) {
    __shared__ int red[256];
    int t = threadIdx.x;
    int acc = 0;
    for (int j = t; j < NB_SCAN; j += 256)
        if (j < blockIdx.x) acc += g_bsum[j];
    red[t] = acc;
    __syncthreads();
    for (int o = 128; o > 0; o >>= 1) {
        if (t < o) red[t] += red[t + o];
        __syncthreads();
    }
    int base = red[0];
    int i = blockIdx.x * 256 + t;
    if (i < N_NODES) {
        int o = g_off[i] + base;
        g_off[i] = o;
        g_cursor[i] = o;
    }
    if (i == 0) g_off[N_NODES] = N_EDGES;
}

// ---------------- K3: scatter edges into dst buckets; re-zero indeg for next run ----
__global__ void k_scatter(const int* __restrict__ ei) {
    int e = blockIdx.x * blockDim.x + threadIdx.x;
    if (e < N_NODES) g_indeg[e] = 0;   // indeg dead after scan1; reset for next replay
    if (e >= N_EDGES) return;
    int s = ei[e];
    int d = ei[N_EDGES + e];
    float norm = g_dinv[s] * g_dinv[d];
    int pos = atomicAdd(&g_cursor[d], 1);
    g_edge[pos] = make_int2(s, __float_as_int(norm));
}

// ---------------- K4: GEMM1  h1 = x @ W1 ----------------
// f32x2 FMA; W staged in shared as ulonglong2 so each LDS.128 feeds TWO FFMA2
// (halves LDS instruction + L1 wavefront count vs LDS.64 — R10 showed L1=79% bound).
__global__ void __launch_bounds__(256) k_gemm1(const float* __restrict__ x,
                                               const float* __restrict__ W1) {
    __shared__ ulonglong2 Wp[128 * 16];   // 32KB: 128 k-rows x 16 pair-of-pairs
    int node = blockIdx.x * 256 + threadIdx.x;

    ull acc[32];
#pragma unroll
    for (int j = 0; j < 32; ++j) acc[j] = 0ull;

#pragma unroll
    for (int chunk = 0; chunk < 2; ++chunk) {
        __syncthreads();   // protect previous chunk's Wp
        {
            const ulonglong2* src = reinterpret_cast<const ulonglong2*>(W1) + chunk * 2048;
            for (int i = threadIdx.x; i < 2048; i += 256) Wp[i] = src[i];
        }
        __syncthreads();

        if (node < N_NODES) {
            const float4* xrow =
                reinterpret_cast<const float4*>(x + (size_t)node * F_IN + chunk * 128);
            for (int k4 = 0; k4 < 32; ++k4) {
                float4 xv = xrow[k4];
                float xa[4] = {xv.x, xv.y, xv.z, xv.w};
#pragma unroll
                for (int kk = 0; kk < 4; ++kk) {
                    ull xs2 = pack2(xa[kk]);
                    const ulonglong2* wr = Wp + (k4 * 4 + kk) * 16;
#pragma unroll
                    for (int j = 0; j < 16; ++j) {
                        ulonglong2 w = wr[j];                // one LDS.128 -> 2 FFMA2
                        acc[2 * j + 0] = fma2(xs2, w.x, acc[2 * j + 0]);
                        acc[2 * j + 1] = fma2(xs2, w.y, acc[2 * j + 1]);
                    }
                }
            }
        }
    }

    if (node < N_NODES) {
        ulonglong2* o = reinterpret_cast<ulonglong2*>(g_h1 + (size_t)node * 32);
#pragma unroll
        for (int j = 0; j < 16; ++j) o[j] = make_ulonglong2(acc[2 * j], acc[2 * j + 1]);
    }
}

// ---------------- K5: fused gather1 + bias + relu + layer2 GEMV ----------------
// One warp per node; lane owns columns [2*lane, 2*lane+1]. (Proven-best R7 form.)
__global__ void __launch_bounds__(256) k_gather1(const float* __restrict__ b1,
                                                 const float* __restrict__ W2) {
    __shared__ float W2s[HID * 2];
    if (threadIdx.x < HID * 2) W2s[threadIdx.x] = W2[threadIdx.x];
    __syncthreads();

    int node = blockIdx.x * 8 + (threadIdx.x >> 5);
    if (node >= N_NODES) return;
    int lane = threadIdx.x & 31;

    float dn = g_dinv[node];

    // self loop: dinv[n]^2 * h1[n]
    float2 hv = g_h1[(size_t)node * 32 + lane];
    float d2 = dn * dn;
    float2 acc = make_float2(hv.x * d2, hv.y * d2);

    int beg = g_off[node], end = g_off[node + 1];
    for (int e = beg; e < end; ++e) {
        int2 en = g_edge[e];                           // warp-uniform broadcast
        float norm = __int_as_float(en.y);
        float2 v = g_h1[(size_t)en.x * 32 + lane];     // coalesced 256B row
        acc.x = fmaf(v.x, norm, acc.x);
        acc.y = fmaf(v.y, norm, acc.y);
    }

    float rx = fmaxf(acc.x + b1[2 * lane + 0], 0.0f);
    float ry = fmaxf(acc.y + b1[2 * lane + 1], 0.0f);

    // layer-2 GEMV partials: msg2[n] = relu_row . W2 (W2 is [HID][2])
    float a0 = rx * W2s[4 * lane + 0] + ry * W2s[4 * lane + 2];
    float a1 = rx * W2s[4 * lane + 1] + ry * W2s[4 * lane + 3];
#pragma unroll
    for (int o = 16; o > 0; o >>= 1) {
        a0 += __shfl_down_sync(0xffffffffu, a0, o);
        a1 += __shfl_down_sync(0xffffffffu, a1, o);
    }
    if (lane == 0) g_msg2[node] = make_float2(a0, a1);
}

// ---------------- K6: fused gather2 + mean-pool (one block per graph) ---------------
__device__ __forceinline__ int lower_bound_i(const int* __restrict__ a, int key) {
    int lo = 0, hi = N_NODES;
    while (lo < hi) {
        int mid = (lo + hi) >> 1;
        if (a[mid] < key) lo = mid + 1; else hi = mid;
    }
    return lo;
}

__global__ void __launch_bounds__(256) k_pool(const int* __restrict__ batch,
                                              const float* __restrict__ b2,
                                              float* __restrict__ out) {
    __shared__ float sx[256], sy[256];
    int g = blockIdx.x;
    int lo = lower_bound_i(batch, g);
    int hi = lower_bound_i(batch, g + 1);
    float bx = b2[0], by = b2[1];
    float ax = 0.0f, ay = 0.0f;
    for (int i = lo + threadIdx.x; i < hi; i += 256) {
        float dn = g_dinv[i];
        float2 m = g_msg2[i];
        float d2 = dn * dn;
        float vx = bx + m.x * d2;
        float vy = by + m.y * d2;
        int beg = g_off[i], end = g_off[i + 1];
        int e = beg;
        for (; e + 2 <= end; e += 2) {
            int2 e0 = g_edge[e];
            int2 e1 = g_edge[e + 1];
            float2 v0 = g_msg2[e0.x];
            float2 v1 = g_msg2[e1.x];
            float n0 = __int_as_float(e0.y);
            float n1 = __int_as_float(e1.y);
            vx = fmaf(v0.x, n0, vx);
            vy = fmaf(v0.y, n0, vy);
            vx = fmaf(v1.x, n1, vx);
            vy = fmaf(v1.y, n1, vy);
        }
        if (e < end) {
            int2 e0 = g_edge[e];
            float n0 = __int_as_float(e0.y);
            float2 v0 = g_msg2[e0.x];
            vx = fmaf(v0.x, n0, vx);
            vy = fmaf(v0.y, n0, vy);
        }
        ax += vx;
        ay += vy;
    }
    sx[threadIdx.x] = ax;
    sy[threadIdx.x] = ay;
    __syncthreads();
    for (int o = 128; o > 0; o >>= 1) {
        if (threadIdx.x < o) {
            sx[threadIdx.x] += sx[threadIdx.x + o];
            sy[threadIdx.x] += sy[threadIdx.x + o];
        }
        __syncthreads();
    }
    if (threadIdx.x == 0) {
        float c = fmaxf((float)(hi - lo), 1.0f);
        out[g * 2 + 0] = sx[0] / c;
        out[g * 2 + 1] = sy[0] / c;
    }
}

// ---------------- launch ----------------
// Capture order keeps k_gemm1 as the 4th kernel launch (ncu -s 5 profiles it).
extern "C" void kernel_launch(void* const* d_in, const int* in_sizes, int n_in,
                              void* d_out, int out_size) {
    const float* x     = (const float*)d_in[0];
    const int*   ei    = (const int*)d_in[1];    // int32
    const int*   batch = (const int*)d_in[2];    // int32
    const float* W1    = (const float*)d_in[3];
    const float* b1    = (const float*)d_in[4];
    const float* W2    = (const float*)d_in[5];
    const float* b2    = (const float*)d_in[6];
    float*       out   = (float*)d_out;

    cudaStream_t s2;
    cudaEvent_t evFork, evJoin;
    cudaStreamCreateWithFlags(&s2, cudaStreamNonBlocking);
    cudaEventCreateWithFlags(&evFork, cudaEventDisableTiming);
    cudaEventCreateWithFlags(&evJoin, cudaEventDisableTiming);

    // Fork point (before any main-stream work).
    cudaEventRecord(evFork, 0);
    cudaStreamWaitEvent(s2, evFork, 0);

    // Main stream: CSR build chain (indeg pre-zeroed by previous run's scatter).
    k_hist<<<(N_EDGES + 255) / 256, 256>>>(ei);        // launch 1
    k_scan1<<<NB_SCAN, 256>>>();                       // launch 2
    k_scan3<<<NB_SCAN, 256>>>();                       // launch 3

    // Side stream: dense projection (depends only on fork event).
    k_gemm1<<<(N_NODES + 255) / 256, 256, 0, s2>>>(x, W1);  // launch 4 (profiled)
    cudaEventRecord(evJoin, s2);

    k_scatter<<<(N_EDGES + 255) / 256, 256>>>(ei);     // launch 5

    // Join: gather1 needs both h1 and the CSR.
    cudaStreamWaitEvent(0, evJoin, 0);
    k_gather1<<<(N_NODES + 7) / 8, 256>>>(b1, W2);     // launch 6
    k_pool<<<N_GRAPHS, 256>>>(batch, b2, out);         // launch 7
}

// round 12
// speedup vs baseline: 1.6528x; 1.0559x over previous
#include <cuda_runtime.h>

#define N_NODES  100000
#define N_EDGES  1600000
#define N_GRAPHS 512
#define F_IN     256
#define HID      64
#define NB_SCAN  ((N_NODES + 255) / 256)   // 391 scan blocks

typedef unsigned long long ull;

// ---------------- scratch (static device globals; no runtime alloc) ----------------
// NOTE: g_indeg relies on zero-init at module load; k_scatter re-zeroes it each run.
__device__ float2 g_h1[(size_t)N_NODES * 32];   // x @ W1, as 32 float2 per node
__device__ int    g_indeg[N_NODES];
__device__ float  g_dinv[N_NODES];
__device__ int    g_off[N_NODES + 1];
__device__ int    g_cursor[N_NODES];
__device__ int    g_bsum[NB_SCAN];
__device__ int2   g_edge[N_EDGES];              // (src, norm-as-bits), bucketed by dst
__device__ float2 g_msg2[N_NODES];              // relu(agg1) @ W2

// ---------------- f32x2 helpers ----------------
__device__ __forceinline__ ull pack2(float v) {
    ull r;
    asm("mov.b64 %0, {%1, %1};" : "=l"(r) : "f"(v));
    return r;
}
__device__ __forceinline__ ull fma2(ull a, ull b, ull c) {
    ull d;
    asm("fma.rn.f32x2 %0, %1, %2, %3;" : "=l"(d) : "l"(a), "l"(b), "l"(c));
    return d;
}

// ---------------- K1: in-degree histogram over dst ----------------
__global__ void k_hist(const int* __restrict__ ei) {
    int e = blockIdx.x * blockDim.x + threadIdx.x;
    if (e < N_EDGES) atomicAdd(&g_indeg[ei[N_EDGES + e]], 1);
}

// ---------------- scan helpers ----------------
__device__ __forceinline__ int warp_incl_scan(int v) {
#pragma unroll
    for (int o = 1; o < 32; o <<= 1) {
        int n = __shfl_up_sync(0xffffffffu, v, o);
        if ((threadIdx.x & 31) >= o) v += n;
    }
    return v;
}

// K2a: per-block exclusive scan of indeg + fused dinv = rsqrt(indeg+1)
__global__ void k_scan1(void) {
    __shared__ int wsum[8];
    __shared__ int woff[8];
    int i = blockIdx.x * 256 + threadIdx.x;
    int v = (i < N_NODES) ? g_indeg[i] : 0;
    if (i < N_NODES) g_dinv[i] = rsqrtf((float)(v + 1));
    int incl = warp_incl_scan(v);
    int lane = threadIdx.x & 31, wid = threadIdx.x >> 5;
    if (lane == 31) wsum[wid] = incl;
    __syncthreads();
    if (threadIdx.x == 0) {
        int r = 0;
#pragma unroll
        for (int w = 0; w < 8; ++w) { woff[w] = r; r += wsum[w]; }
        g_bsum[blockIdx.x] = r;
    }
    __syncthreads();
    if (i < N_NODES) g_off[i] = incl - v + woff[wid];
}

// K2b: fused block-sum prefix + finalize offsets
__global__ void k_scan3(void) {
    __shared__ int red[256];
    int t = threadIdx.x;
    int acc = 0;
    for (int j = t; j < NB_SCAN; j += 256)
        if (j < blockIdx.x) acc += g_bsum[j];
    red[t] = acc;
    __syncthreads();
    for (int o = 128; o > 0; o >>= 1) {
        if (t < o) red[t] += red[t + o];
        __syncthreads();
    }
    int base = red[0];
    int i = blockIdx.x * 256 + t;
    if (i < N_NODES) {
        int o = g_off[i] + base;
        g_off[i] = o;
        g_cursor[i] = o;
    }
    if (i == 0) g_off[N_NODES] = N_EDGES;
}

// ---------------- K3: scatter edges into dst buckets; re-zero indeg for next run ----
__global__ void k_scatter(const int* __restrict__ ei) {
    int e = blockIdx.x * blockDim.x + threadIdx.x;
    if (e < N_NODES) g_indeg[e] = 0;   // indeg dead after scan1; reset for next replay
    if (e >= N_EDGES) return;
    int s = ei[e];
    int d = ei[N_EDGES + e];
    float norm = g_dinv[s] * g_dinv[d];
    int pos = atomicAdd(&g_cursor[d], 1);
    g_edge[pos] = make_int2(s, __float_as_int(norm));
}

// ---------------- K4: GEMM1  h1 = x @ W1  (2D register-tiled, f32x2) ----------------
// Block: 128 nodes x 64 cols, K-tile 32. Thread (ng=t>>3, cg=t&7): 4 nodes x 8 cols.
// Per k: 1 LDS.128 (4 node x-vals) + 2 LDS.128 (8 w cols, lanes DISTINCT data)
// + 16 FFMA2. xs is k-major with XOR-swizzled 4-node chunks (conflict-bounded
// transpose stores AND aligned vector reads).
#define MT 128
#define KT 32
__global__ void __launch_bounds__(256) k_gemm1(const float* __restrict__ x,
                                               const float* __restrict__ W1) {
    __shared__ float xs[KT][MT];    // [k][swizzled node] 16KB
    __shared__ float ws[KT][HID];   // [k][col]           8KB
    int t = threadIdx.x;
    int ng = t >> 3;                // 0..31 : nodes ng*4 .. ng*4+3
    int cg = t & 7;                 // 0..7  : cols  cg*8 .. cg*8+7
    int base = blockIdx.x * MT;

    ull acc[4][4];                  // [node i][colpair p] -> cols cg*8+2p, +1
#pragma unroll
    for (int i = 0; i < 4; ++i)
#pragma unroll
        for (int p = 0; p < 4; ++p) acc[i][p] = 0ull;

    // loader decomposition of idx in [0,1024): node_lo=idx&3, k4=(idx>>2)&7, nh=idx>>5
    for (int kt = 0; kt < F_IN; kt += KT) {
        __syncthreads();
#pragma unroll
        for (int r = 0; r < 4; ++r) {
            int idx = t + r * 256;
            int node_lo = idx & 3;
            int k4 = (idx >> 2) & 7;
            int nh = idx >> 5;                 // node chunk 0..31
            int gn = base + nh * 4 + node_lo;
            float4 v = make_float4(0.f, 0.f, 0.f, 0.f);
            if (gn < N_NODES)
                v = *reinterpret_cast<const float4*>(x + (size_t)gn * F_IN + kt + k4 * 4);
            int k0 = k4 * 4;
            xs[k0 + 0][(((nh ^ (k0 + 0)) & 31) << 2) + node_lo] = v.x;
            xs[k0 + 1][(((nh ^ (k0 + 1)) & 31) << 2) + node_lo] = v.y;
            xs[k0 + 2][(((nh ^ (k0 + 2)) & 31) << 2) + node_lo] = v.z;
            xs[k0 + 3][(((nh ^ (k0 + 3)) & 31) << 2) + node_lo] = v.w;
        }
#pragma unroll
        for (int r = 0; r < 2; ++r) {
            int idx = t + r * 256;             // 512 float4 = 32x64 floats
            reinterpret_cast<float4*>(ws)[idx] =
                reinterpret_cast<const float4*>(W1 + (size_t)kt * HID)[idx];
        }
        __syncthreads();

#pragma unroll 4
        for (int k = 0; k < KT; ++k) {
            float4 xv = *reinterpret_cast<const float4*>(&xs[k][((ng ^ k) & 31) << 2]);
            const ulonglong2* wp = reinterpret_cast<const ulonglong2*>(&ws[k][cg * 8]);
            ulonglong2 w0 = wp[0];
            ulonglong2 w1 = wp[1];
            float xa[4] = {xv.x, xv.y, xv.z, xv.w};
#pragma unroll
            for (int i = 0; i < 4; ++i) {
                ull xp = pack2(xa[i]);
                acc[i][0] = fma2(xp, w0.x, acc[i][0]);
                acc[i][1] = fma2(xp, w0.y, acc[i][1]);
                acc[i][2] = fma2(xp, w1.x, acc[i][2]);
                acc[i][3] = fma2(xp, w1.y, acc[i][3]);
            }
        }
    }

#pragma unroll
    for (int i = 0; i < 4; ++i) {
        int gn = base + ng * 4 + i;
        if (gn < N_NODES) {
            ull* hp = reinterpret_cast<ull*>(g_h1) + (size_t)gn * 32 + cg * 4;
            *reinterpret_cast<ulonglong2*>(hp) = make_ulonglong2(acc[i][0], acc[i][1]);
            *reinterpret_cast<ulonglong2*>(hp + 2) = make_ulonglong2(acc[i][2], acc[i][3]);
        }
    }
}

// ---------------- K5: fused gather1 + bias + relu + layer2 GEMV ----------------
// One warp per node; lane owns columns [2*lane, 2*lane+1]. (Proven-best R7 form.)
__global__ void __launch_bounds__(256) k_gather1(const float* __restrict__ b1,
                                                 const float* __restrict__ W2) {
    __shared__ float W2s[HID * 2];
    if (threadIdx.x < HID * 2) W2s[threadIdx.x] = W2[threadIdx.x];
    __syncthreads();

    int node = blockIdx.x * 8 + (threadIdx.x >> 5);
    if (node >= N_NODES) return;
    int lane = threadIdx.x & 31;

    float dn = g_dinv[node];

    // self loop: dinv[n]^2 * h1[n]
    float2 hv = g_h1[(size_t)node * 32 + lane];
    float d2 = dn * dn;
    float2 acc = make_float2(hv.x * d2, hv.y * d2);

    int beg = g_off[node], end = g_off[node + 1];
    for (int e = beg; e < end; ++e) {
        int2 en = g_edge[e];                           // warp-uniform broadcast
        float norm = __int_as_float(en.y);
        float2 v = g_h1[(size_t)en.x * 32 + lane];     // coalesced 256B row
        acc.x = fmaf(v.x, norm, acc.x);
        acc.y = fmaf(v.y, norm, acc.y);
    }

    float rx = fmaxf(acc.x + b1[2 * lane + 0], 0.0f);
    float ry = fmaxf(acc.y + b1[2 * lane + 1], 0.0f);

    // layer-2 GEMV partials: msg2[n] = relu_row . W2 (W2 is [HID][2])
    float a0 = rx * W2s[4 * lane + 0] + ry * W2s[4 * lane + 2];
    float a1 = rx * W2s[4 * lane + 1] + ry * W2s[4 * lane + 3];
#pragma unroll
    for (int o = 16; o > 0; o >>= 1) {
        a0 += __shfl_down_sync(0xffffffffu, a0, o);
        a1 += __shfl_down_sync(0xffffffffu, a1, o);
    }
    if (lane == 0) g_msg2[node] = make_float2(a0, a1);
}

// ---------------- K6: fused gather2 + mean-pool (one block per graph) ---------------
__device__ __forceinline__ int lower_bound_i(const int* __restrict__ a, int key) {
    int lo = 0, hi = N_NODES;
    while (lo < hi) {
        int mid = (lo + hi) >> 1;
        if (a[mid] < key) lo = mid + 1; else hi = mid;
    }
    return lo;
}

__global__ void __launch_bounds__(256) k_pool(const int* __restrict__ batch,
                                              const float* __restrict__ b2,
                                              float* __restrict__ out) {
    __shared__ float sx[256], sy[256];
    int g = blockIdx.x;
    int lo = lower_bound_i(batch, g);
    int hi = lower_bound_i(batch, g + 1);
    float bx = b2[0], by = b2[1];
    float ax = 0.0f, ay = 0.0f;
    for (int i = lo + threadIdx.x; i < hi; i += 256) {
        float dn = g_dinv[i];
        float2 m = g_msg2[i];
        float d2 = dn * dn;
        float vx = bx + m.x * d2;
        float vy = by + m.y * d2;
        int beg = g_off[i], end = g_off[i + 1];
        int e = beg;
        for (; e + 2 <= end; e += 2) {
            int2 e0 = g_edge[e];
            int2 e1 = g_edge[e + 1];
            float2 v0 = g_msg2[e0.x];
            float2 v1 = g_msg2[e1.x];
            float n0 = __int_as_float(e0.y);
            float n1 = __int_as_float(e1.y);
            vx = fmaf(v0.x, n0, vx);
            vy = fmaf(v0.y, n0, vy);
            vx = fmaf(v1.x, n1, vx);
            vy = fmaf(v1.y, n1, vy);
        }
        if (e < end) {
            int2 e0 = g_edge[e];
            float n0 = __int_as_float(e0.y);
            float2 v0 = g_msg2[e0.x];
            vx = fmaf(v0.x, n0, vx);
            vy = fmaf(v0.y, n0, vy);
        }
        ax += vx;
        ay += vy;
    }
    sx[threadIdx.x] = ax;
    sy[threadIdx.x] = ay;
    __syncthreads();
    for (int o = 128; o > 0; o >>= 1) {
        if (threadIdx.x < o) {
            sx[threadIdx.x] += sx[threadIdx.x + o];
            sy[threadIdx.x] += sy[threadIdx.x + o];
        }
        __syncthreads();
    }
    if (threadIdx.x == 0) {
        float c = fmaxf((float)(hi - lo), 1.0f);
        out[g * 2 + 0] = sx[0] / c;
        out[g * 2 + 1] = sy[0] / c;
    }
}

// ---------------- launch ----------------
// Capture order keeps k_gemm1 as the 4th kernel launch (ncu -s 5 profiles it).
extern "C" void kernel_launch(void* const* d_in, const int* in_sizes, int n_in,
                              void* d_out, int out_size) {
    const float* x     = (const float*)d_in[0];
    const int*   ei    = (const int*)d_in[1];    // int32
    const int*   batch = (const int*)d_in[2];    // int32
    const float* W1    = (const float*)d_in[3];
    const float* b1    = (const float*)d_in[4];
    const float* W2    = (const float*)d_in[5];
    const float* b2    = (const float*)d_in[6];
    float*       out   = (float*)d_out;

    cudaStream_t s2;
    cudaEvent_t evFork, evJoin;
    cudaStreamCreateWithFlags(&s2, cudaStreamNonBlocking);
    cudaEventCreateWithFlags(&evFork, cudaEventDisableTiming);
    cudaEventCreateWithFlags(&evJoin, cudaEventDisableTiming);

    // Fork point (before any main-stream work).
    cudaEventRecord(evFork, 0);
    cudaStreamWaitEvent(s2, evFork, 0);

    // Main stream: CSR build chain (indeg pre-zeroed by previous run's scatter).
    k_hist<<<(N_EDGES + 255) / 256, 256>>>(ei);        // launch 1
    k_scan1<<<NB_SCAN, 256>>>();                       // launch 2
    k_scan3<<<NB_SCAN, 256>>>();                       // launch 3

    // Side stream: dense projection (depends only on fork event).
    k_gemm1<<<(N_NODES + MT - 1) / MT, 256, 0, s2>>>(x, W1);  // launch 4 (profiled)
    cudaEventRecord(evJoin, s2);

    k_scatter<<<(N_EDGES + 255) / 256, 256>>>(ei);     // launch 5

    // Join: gather1 needs both h1 and the CSR.
    cudaStreamWaitEvent(0, evJoin, 0);
    k_gather1<<<(N_NODES + 7) / 8, 256>>>(b1, W2);     // launch 6
    k_pool<<<N_GRAPHS, 256>>>(batch, b2, out);         // launch 7
}

// round 13
// speedup vs baseline: 2.1082x; 1.2755x over previous
#include <cuda_runtime.h>

#define N_NODES  100000
#define N_EDGES  1600000
#define N_GRAPHS 512
#define F_IN     256
#define HID      64
#define NB_SCAN  ((N_NODES + 255) / 256)   // 391 scan blocks

typedef unsigned long long ull;

// ---------------- scratch (static device globals; no runtime alloc) ----------------
// NOTE: g_indeg relies on zero-init at module load; k_scatter re-zeroes it each run.
__device__ float2 g_h1[(size_t)N_NODES * 32];   // x @ W1, as 32 float2 per node
__device__ int    g_indeg[N_NODES];
__device__ float  g_dinv[N_NODES];
__device__ int    g_off[N_NODES + 1];
__device__ int    g_cursor[N_NODES];
__device__ int    g_bsum[NB_SCAN];
__device__ int2   g_edge[N_EDGES];              // (src, norm-as-bits), bucketed by dst
__device__ float2 g_msg2[N_NODES];              // relu(agg1) @ W2

// ---------------- f32x2 helpers ----------------
__device__ __forceinline__ ull pack2(float v) {
    ull r;
    asm("mov.b64 %0, {%1, %1};" : "=l"(r) : "f"(v));
    return r;
}
__device__ __forceinline__ ull fma2(ull a, ull b, ull c) {
    ull d;
    asm("fma.rn.f32x2 %0, %1, %2, %3;" : "=l"(d) : "l"(a), "l"(b), "l"(c));
    return d;
}

// ---------------- K1: in-degree histogram over dst ----------------
__global__ void k_hist(const int* __restrict__ ei) {
    int e = blockIdx.x * blockDim.x + threadIdx.x;
    if (e < N_EDGES) atomicAdd(&g_indeg[ei[N_EDGES + e]], 1);
}

// ---------------- scan helpers ----------------
__device__ __forceinline__ int warp_incl_scan(int v) {
#pragma unroll
    for (int o = 1; o < 32; o <<= 1) {
        int n = __shfl_up_sync(0xffffffffu, v, o);
        if ((threadIdx.x & 31) >= o) v += n;
    }
    return v;
}

// K2a: per-block exclusive scan of indeg + fused dinv = rsqrt(indeg+1)
__global__ void k_scan1(void) {
    __shared__ int wsum[8];
    __shared__ int woff[8];
    int i = blockIdx.x * 256 + threadIdx.x;
    int v = (i < N_NODES) ? g_indeg[i] : 0;
    if (i < N_NODES) g_dinv[i] = rsqrtf((float)(v + 1));
    int incl = warp_incl_scan(v);
    int lane = threadIdx.x & 31, wid = threadIdx.x >> 5;
    if (lane == 31) wsum[wid] = incl;
    __syncthreads();
    if (threadIdx.x == 0) {
        int r = 0;
#pragma unroll
        for (int w = 0; w < 8; ++w) { woff[w] = r; r += wsum[w]; }
        g_bsum[blockIdx.x] = r;
    }
    __syncthreads();
    if (i < N_NODES) g_off[i] = incl - v + woff[wid];
}

// K2b: fused block-sum prefix + finalize offsets
__global__ void k_scan3(void) {
    __shared__ int red[256];
    int t = threadIdx.x;
    int acc = 0;
    for (int j = t; j < NB_SCAN; j += 256)
        if (j < blockIdx.x) acc += g_bsum[j];
    red[t] = acc;
    __syncthreads();
    for (int o = 128; o > 0; o >>= 1) {
        if (t < o) red[t] += red[t + o];
        __syncthreads();
    }
    int base = red[0];
    int i = blockIdx.x * 256 + t;
    if (i < N_NODES) {
        int o = g_off[i] + base;
        g_off[i] = o;
        g_cursor[i] = o;
    }
    if (i == 0) g_off[N_NODES] = N_EDGES;
}

// ---------------- K3: scatter edges into dst buckets; re-zero indeg for next run ----
__global__ void k_scatter(const int* __restrict__ ei) {
    int e = blockIdx.x * blockDim.x + threadIdx.x;
    if (e < N_NODES) g_indeg[e] = 0;   // indeg dead after scan1; reset for next replay
    if (e >= N_EDGES) return;
    int s = ei[e];
    int d = ei[N_EDGES + e];
    float norm = g_dinv[s] * g_dinv[d];
    int pos = atomicAdd(&g_cursor[d], 1);
    g_edge[pos] = make_int2(s, __float_as_int(norm));
}

// ---------------- K4: GEMM1  h1 = x @ W1  (2D tiled, f32x2, conflict-free smem) -----
// Block: 128 nodes x 64 cols, K-tile 32. Thread (ng=t>>3, cg=t&7):
//   4 nodes (ng*4..+3) x 8 cols ({cg*4..+3} U {32+cg*4..+3}).
// ws: lanes at 16B stride over 32 banks -> conflict-free w-LDS.128.
// xs: slot p = (nh ^ (r>>2) ^ ((r&3)<<3)) & 31 puts k4 in p's LOW bits ->
//   transpose STS covers all 32 banks (k4 x node_lo), reads stay 1 wf.
#define MT 128
#define KT 32
__global__ void __launch_bounds__(256) k_gemm1(const float* __restrict__ x,
                                               const float* __restrict__ W1) {
    __shared__ float xs[KT][MT];    // [k][swizzled slot*4 + node_lo] 16KB
    __shared__ float ws[KT][HID];   // [k][col]                       8KB
    int t = threadIdx.x;
    int ng = t >> 3;                // 0..31
    int cg = t & 7;                 // 0..7
    int base = blockIdx.x * MT;

    ull acc[4][4];                  // [node i][p]: p=0,1 -> cols cg*4+2p ; p=2,3 -> 32+cg*4+2(p-2)
#pragma unroll
    for (int i = 0; i < 4; ++i)
#pragma unroll
        for (int p = 0; p < 4; ++p) acc[i][p] = 0ull;

    for (int kt = 0; kt < F_IN; kt += KT) {
        __syncthreads();
#pragma unroll
        for (int r = 0; r < 4; ++r) {
            int idx = t + r * 256;
            int node_lo = idx & 3;
            int k4 = (idx >> 2) & 7;
            int nh = idx >> 5;                 // node chunk 0..31
            int gn = base + nh * 4 + node_lo;
            float4 v = make_float4(0.f, 0.f, 0.f, 0.f);
            if (gn < N_NODES)
                v = *reinterpret_cast<const float4*>(x + (size_t)gn * F_IN + kt + k4 * 4);
            float va[4] = {v.x, v.y, v.z, v.w};
#pragma unroll
            for (int i = 0; i < 4; ++i) {
                int row = k4 * 4 + i;
                int p = (nh ^ k4 ^ (i << 3)) & 31;
                xs[row][(p << 2) + node_lo] = va[i];
            }
        }
#pragma unroll
        for (int r = 0; r < 2; ++r) {
            int idx = t + r * 256;             // 512 float4 = 32x64 floats
            reinterpret_cast<float4*>(ws)[idx] =
                reinterpret_cast<const float4*>(W1 + (size_t)kt * HID)[idx];
        }
        __syncthreads();

#pragma unroll 8
        for (int k = 0; k < KT; ++k) {
            int p = (ng ^ (k >> 2) ^ ((k & 3) << 3)) & 31;
            float4 xv = *reinterpret_cast<const float4*>(&xs[k][p << 2]);
            ulonglong2 w0 = *reinterpret_cast<const ulonglong2*>(&ws[k][cg * 4]);
            ulonglong2 w1 = *reinterpret_cast<const ulonglong2*>(&ws[k][32 + cg * 4]);
            float xa[4] = {xv.x, xv.y, xv.z, xv.w};
#pragma unroll
            for (int i = 0; i < 4; ++i) {
                ull xp = pack2(xa[i]);
                acc[i][0] = fma2(xp, w0.x, acc[i][0]);
                acc[i][1] = fma2(xp, w0.y, acc[i][1]);
                acc[i][2] = fma2(xp, w1.x, acc[i][2]);
                acc[i][3] = fma2(xp, w1.y, acc[i][3]);
            }
        }
    }

#pragma unroll
    for (int i = 0; i < 4; ++i) {
        int gn = base + ng * 4 + i;
        if (gn < N_NODES) {
            ull* hp = reinterpret_cast<ull*>(g_h1) + (size_t)gn * 32 + cg * 2;
            *reinterpret_cast<ulonglong2*>(hp) = make_ulonglong2(acc[i][0], acc[i][1]);
            *reinterpret_cast<ulonglong2*>(hp + 16) = make_ulonglong2(acc[i][2], acc[i][3]);
        }
    }
}

// ---------------- K5: fused gather1 + bias + relu + layer2 GEMV ----------------
// One warp per node; lane owns columns [2*lane, 2*lane+1]. (Proven-best R7 form.)
__global__ void __launch_bounds__(256) k_gather1(const float* __restrict__ b1,
                                                 const float* __restrict__ W2) {
    __shared__ float W2s[HID * 2];
    if (threadIdx.x < HID * 2) W2s[threadIdx.x] = W2[threadIdx.x];
    __syncthreads();

    int node = blockIdx.x * 8 + (threadIdx.x >> 5);
    if (node >= N_NODES) return;
    int lane = threadIdx.x & 31;

    float dn = g_dinv[node];

    // self loop: dinv[n]^2 * h1[n]
    float2 hv = g_h1[(size_t)node * 32 + lane];
    float d2 = dn * dn;
    float2 acc = make_float2(hv.x * d2, hv.y * d2);

    int beg = g_off[node], end = g_off[node + 1];
    for (int e = beg; e < end; ++e) {
        int2 en = g_edge[e];                           // warp-uniform broadcast
        float norm = __int_as_float(en.y);
        float2 v = g_h1[(size_t)en.x * 32 + lane];     // coalesced 256B row
        acc.x = fmaf(v.x, norm, acc.x);
        acc.y = fmaf(v.y, norm, acc.y);
    }

    float rx = fmaxf(acc.x + b1[2 * lane + 0], 0.0f);
    float ry = fmaxf(acc.y + b1[2 * lane + 1], 0.0f);

    // layer-2 GEMV partials: msg2[n] = relu_row . W2 (W2 is [HID][2])
    float a0 = rx * W2s[4 * lane + 0] + ry * W2s[4 * lane + 2];
    float a1 = rx * W2s[4 * lane + 1] + ry * W2s[4 * lane + 3];
#pragma unroll
    for (int o = 16; o > 0; o >>= 1) {
        a0 += __shfl_down_sync(0xffffffffu, a0, o);
        a1 += __shfl_down_sync(0xffffffffu, a1, o);
    }
    if (lane == 0) g_msg2[node] = make_float2(a0, a1);
}

// ---------------- K6: fused gather2 + mean-pool (one block per graph) ---------------
__device__ __forceinline__ int lower_bound_i(const int* __restrict__ a, int key) {
    int lo = 0, hi = N_NODES;
    while (lo < hi) {
        int mid = (lo + hi) >> 1;
        if (a[mid] < key) lo = mid + 1; else hi = mid;
    }
    return lo;
}

__global__ void __launch_bounds__(256) k_pool(const int* __restrict__ batch,
                                              const float* __restrict__ b2,
                                              float* __restrict__ out) {
    __shared__ float sx[256], sy[256];
    int g = blockIdx.x;
    int lo = lower_bound_i(batch, g);
    int hi = lower_bound_i(batch, g + 1);
    float bx = b2[0], by = b2[1];
    float ax = 0.0f, ay = 0.0f;
    for (int i = lo + threadIdx.x; i < hi; i += 256) {
        float dn = g_dinv[i];
        float2 m = g_msg2[i];
        float d2 = dn * dn;
        float vx = bx + m.x * d2;
        float vy = by + m.y * d2;
        int beg = g_off[i], end = g_off[i + 1];
        int e = beg;
        for (; e + 2 <= end; e += 2) {
            int2 e0 = g_edge[e];
            int2 e1 = g_edge[e + 1];
            float2 v0 = g_msg2[e0.x];
            float2 v1 = g_msg2[e1.x];
            float n0 = __int_as_float(e0.y);
            float n1 = __int_as_float(e1.y);
            vx = fmaf(v0.x, n0, vx);
            vy = fmaf(v0.y, n0, vy);
            vx = fmaf(v1.x, n1, vx);
            vy = fmaf(v1.y, n1, vy);
        }
        if (e < end) {
            int2 e0 = g_edge[e];
            float n0 = __int_as_float(e0.y);
            float2 v0 = g_msg2[e0.x];
            vx = fmaf(v0.x, n0, vx);
            vy = fmaf(v0.y, n0, vy);
        }
        ax += vx;
        ay += vy;
    }
    sx[threadIdx.x] = ax;
    sy[threadIdx.x] = ay;
    __syncthreads();
    for (int o = 128; o > 0; o >>= 1) {
        if (threadIdx.x < o) {
            sx[threadIdx.x] += sx[threadIdx.x + o];
            sy[threadIdx.x] += sy[threadIdx.x + o];
        }
        __syncthreads();
    }
    if (threadIdx.x == 0) {
        float c = fmaxf((float)(hi - lo), 1.0f);
        out[g * 2 + 0] = sx[0] / c;
        out[g * 2 + 1] = sy[0] / c;
    }
}

// ---------------- launch ----------------
// Capture order keeps k_gemm1 as the 4th kernel launch (ncu -s 5 profiles it).
extern "C" void kernel_launch(void* const* d_in, const int* in_sizes, int n_in,
                              void* d_out, int out_size) {
    const float* x     = (const float*)d_in[0];
    const int*   ei    = (const int*)d_in[1];    // int32
    const int*   batch = (const int*)d_in[2];    // int32
    const float* W1    = (const float*)d_in[3];
    const float* b1    = (const float*)d_in[4];
    const float* W2    = (const float*)d_in[5];
    const float* b2    = (const float*)d_in[6];
    float*       out   = (float*)d_out;

    cudaStream_t s2;
    cudaEvent_t evFork, evJoin;
    cudaStreamCreateWithFlags(&s2, cudaStreamNonBlocking);
    cudaEventCreateWithFlags(&evFork, cudaEventDisableTiming);
    cudaEventCreateWithFlags(&evJoin, cudaEventDisableTiming);

    // Fork point (before any main-stream work).
    cudaEventRecord(evFork, 0);
    cudaStreamWaitEvent(s2, evFork, 0);

    // Main stream: CSR build chain (indeg pre-zeroed by previous run's scatter).
    k_hist<<<(N_EDGES + 255) / 256, 256>>>(ei);        // launch 1
    k_scan1<<<NB_SCAN, 256>>>();                       // launch 2
    k_scan3<<<NB_SCAN, 256>>>();                       // launch 3

    // Side stream: dense projection (depends only on fork event).
    k_gemm1<<<(N_NODES + MT - 1) / MT, 256, 0, s2>>>(x, W1);  // launch 4 (profiled)
    cudaEventRecord(evJoin, s2);

    k_scatter<<<(N_EDGES + 255) / 256, 256>>>(ei);     // launch 5

    // Join: gather1 needs both h1 and the CSR.
    cudaStreamWaitEvent(0, evJoin, 0);
    k_gather1<<<(N_NODES + 7) / 8, 256>>>(b1, W2);     // launch 6
    k_pool<<<N_GRAPHS, 256>>>(batch, b2, out);         // launch 7
}

// round 14
// speedup vs baseline: 2.6332x; 1.2490x over previous
#include <cuda_runtime.h>

#define N_NODES  100000
#define N_EDGES  1600000
#define N_GRAPHS 512
#define F_IN     256
#define HID      64
#define NB_SCAN  ((N_NODES + 255) / 256)   // 391 scan blocks

typedef unsigned long long ull;

// ---------------- scratch (static device globals; no runtime alloc) ----------------
// NOTE: g_indeg relies on zero-init at module load; k_scatter re-zeroes it each run.
__device__ float2 g_h1[(size_t)N_NODES * 32];   // x @ W1, as 32 float2 per node
__device__ int    g_indeg[N_NODES];
__device__ float  g_dinv[N_NODES];
__device__ int    g_off[N_NODES + 1];
__device__ int    g_cursor[N_NODES];
__device__ int    g_bsum[NB_SCAN];
__device__ int2   g_edge[N_EDGES];              // (src, norm-as-bits), bucketed by dst
__device__ float2 g_msg2[N_NODES];              // relu(agg1) @ W2

// ---------------- tf32 / mma helpers ----------------
__device__ __forceinline__ unsigned tf32cvt(float f) {
    unsigned r;
    asm("cvt.rna.tf32.f32 %0, %1;" : "=r"(r) : "f"(f));
    return r;
}
__device__ __forceinline__ void mma_tf32(float d[4],
                                         unsigned a0, unsigned a1, unsigned a2, unsigned a3,
                                         unsigned b0, unsigned b1) {
    asm volatile(
        "mma.sync.aligned.m16n8k8.row.col.f32.tf32.tf32.f32 "
        "{%0,%1,%2,%3}, {%4,%5,%6,%7}, {%8,%9}, {%0,%1,%2,%3};"
        : "+f"(d[0]), "+f"(d[1]), "+f"(d[2]), "+f"(d[3])
        : "r"(a0), "r"(a1), "r"(a2), "r"(a3), "r"(b0), "r"(b1));
}

// ---------------- K1: in-degree histogram over dst ----------------
__global__ void k_hist(const int* __restrict__ ei) {
    int e = blockIdx.x * blockDim.x + threadIdx.x;
    if (e < N_EDGES) atomicAdd(&g_indeg[ei[N_EDGES + e]], 1);
}

// ---------------- scan helpers ----------------
__device__ __forceinline__ int warp_incl_scan(int v) {
#pragma unroll
    for (int o = 1; o < 32; o <<= 1) {
        int n = __shfl_up_sync(0xffffffffu, v, o);
        if ((threadIdx.x & 31) >= o) v += n;
    }
    return v;
}

// K2a: per-block exclusive scan of indeg + fused dinv = rsqrt(indeg+1)
__global__ void k_scan1(void) {
    __shared__ int wsum[8];
    __shared__ int woff[8];
    int i = blockIdx.x * 256 + threadIdx.x;
    int v = (i < N_NODES) ? g_indeg[i] : 0;
    if (i < N_NODES) g_dinv[i] = rsqrtf((float)(v + 1));
    int incl = warp_incl_scan(v);
    int lane = threadIdx.x & 31, wid = threadIdx.x >> 5;
    if (lane == 31) wsum[wid] = incl;
    __syncthreads();
    if (threadIdx.x == 0) {
        int r = 0;
#pragma unroll
        for (int w = 0; w < 8; ++w) { woff[w] = r; r += wsum[w]; }
        g_bsum[blockIdx.x] = r;
    }
    __syncthreads();
    if (i < N_NODES) g_off[i] = incl - v + woff[wid];
}

// K2b: fused block-sum prefix + finalize offsets
__global__ void k_scan3(void) {
    __shared__ int red[256];
    int t = threadIdx.x;
    int acc = 0;
    for (int j = t; j < NB_SCAN; j += 256)
        if (j < blockIdx.x) acc += g_bsum[j];
    red[t] = acc;
    __syncthreads();
    for (int o = 128; o > 0; o >>= 1) {
        if (t < o) red[t] += red[t + o];
        __syncthreads();
    }
    int base = red[0];
    int i = blockIdx.x * 256 + t;
    if (i < N_NODES) {
        int o = g_off[i] + base;
        g_off[i] = o;
        g_cursor[i] = o;
    }
    if (i == 0) g_off[N_NODES] = N_EDGES;
}

// ---------------- K3: scatter edges into dst buckets; re-zero indeg for next run ----
__global__ void k_scatter(const int* __restrict__ ei) {
    int e = blockIdx.x * blockDim.x + threadIdx.x;
    if (e < N_NODES) g_indeg[e] = 0;   // indeg dead after scan1; reset for next replay
    if (e >= N_EDGES) return;
    int s = ei[e];
    int d = ei[N_EDGES + e];
    float norm = g_dinv[s] * g_dinv[d];
    int pos = atomicAdd(&g_cursor[d], 1);
    g_edge[pos] = make_int2(s, __float_as_int(norm));
}

// ---------------- K4: GEMM1  h1 = x @ W1  (tf32 mma.sync tensor cores) --------------
// Block: 8 warps, tile m128 x n64. Warp w: rows w*16..w*16+15, all 64 cols
// (8 n-tiles of m16n8k8). K staged in KT=32 chunks.
// xs[128][36]: A-frag bank = (4g+c)%32 -> conflict-free; 144B rows (16B aligned).
// ws[32][72]:  B-frag bank = (8c+g)%32 -> conflict-free; 288B rows (16B aligned).
#define MT 128
#define KT 32
#define XPAD 36
#define WPAD 72
__global__ void __launch_bounds__(256) k_gemm1(const float* __restrict__ x,
                                               const float* __restrict__ W1) {
    __shared__ unsigned xs[MT][XPAD];   // [node][k] tf32 bits, 18KB
    __shared__ unsigned ws[KT][WPAD];   // [k][col]  tf32 bits,  9KB
    int t = threadIdx.x;
    int w = t >> 5;                     // warp 0..7
    int lane = t & 31;
    int g = lane >> 2;                  // 0..7
    int c = lane & 3;                   // 0..3
    int mb = w * 16;
    int base = blockIdx.x * MT;

    float acc[8][4];                    // [n-tile][frag]
#pragma unroll
    for (int nt = 0; nt < 8; ++nt)
#pragma unroll
        for (int i = 0; i < 4; ++i) acc[nt][i] = 0.0f;

    for (int kt = 0; kt < F_IN; kt += KT) {
        __syncthreads();
        // load X tile: 128 nodes x 32 k (1024 float4), coalesced, tf32-converted
#pragma unroll
        for (int r = 0; r < 4; ++r) {
            int idx = t + r * 256;
            int node = idx >> 3;
            int c4 = idx & 7;
            int gn = base + node;
            float4 v = make_float4(0.f, 0.f, 0.f, 0.f);
            if (gn < N_NODES)
                v = *reinterpret_cast<const float4*>(x + (size_t)gn * F_IN + kt + c4 * 4);
            uint4 u = make_uint4(tf32cvt(v.x), tf32cvt(v.y), tf32cvt(v.z), tf32cvt(v.w));
            *reinterpret_cast<uint4*>(&xs[node][c4 * 4]) = u;
        }
        // load W tile: 32 k x 64 cols (512 float4)
#pragma unroll
        for (int r = 0; r < 2; ++r) {
            int idx = t + r * 256;
            int row = idx >> 4;
            int c4 = idx & 15;
            float4 v = *reinterpret_cast<const float4*>(W1 + (size_t)(kt + row) * HID + c4 * 4);
            uint4 u = make_uint4(tf32cvt(v.x), tf32cvt(v.y), tf32cvt(v.z), tf32cvt(v.w));
            *reinterpret_cast<uint4*>(&ws[row][c4 * 4]) = u;
        }
        __syncthreads();

#pragma unroll
        for (int k8 = 0; k8 < KT; k8 += 8) {
            unsigned a0 = xs[mb + g][k8 + c];
            unsigned a1 = xs[mb + g + 8][k8 + c];
            unsigned a2 = xs[mb + g][k8 + c + 4];
            unsigned a3 = xs[mb + g + 8][k8 + c + 4];
#pragma unroll
            for (int nt = 0; nt < 8; ++nt) {
                unsigned b0 = ws[k8 + c][nt * 8 + g];
                unsigned b1 = ws[k8 + c + 4][nt * 8 + g];
                mma_tf32(acc[nt], a0, a1, a2, a3, b0, b1);
            }
        }
    }

    // store: thread owns rows (mb+g, mb+g+8), cols nt*8 + c*2 (+1)
    int gn0 = base + mb + g;
    int gn1 = gn0 + 8;
#pragma unroll
    for (int nt = 0; nt < 8; ++nt) {
        int f2 = nt * 4 + c;            // float2 index within the 32-float2 row
        if (gn0 < N_NODES) g_h1[(size_t)gn0 * 32 + f2] = make_float2(acc[nt][0], acc[nt][1]);
        if (gn1 < N_NODES) g_h1[(size_t)gn1 * 32 + f2] = make_float2(acc[nt][2], acc[nt][3]);
    }
}

// ---------------- K5: fused gather1 + bias + relu + layer2 GEMV ----------------
// One warp per node; lane owns columns [2*lane, 2*lane+1]. (Proven-best R7 form.)
__global__ void __launch_bounds__(256) k_gather1(const float* __restrict__ b1,
                                                 const float* __restrict__ W2) {
    __shared__ float W2s[HID * 2];
    if (threadIdx.x < HID * 2) W2s[threadIdx.x] = W2[threadIdx.x];
    __syncthreads();

    int node = blockIdx.x * 8 + (threadIdx.x >> 5);
    if (node >= N_NODES) return;
    int lane = threadIdx.x & 31;

    float dn = g_dinv[node];

    // self loop: dinv[n]^2 * h1[n]
    float2 hv = g_h1[(size_t)node * 32 + lane];
    float d2 = dn * dn;
    float2 acc = make_float2(hv.x * d2, hv.y * d2);

    int beg = g_off[node], end = g_off[node + 1];
    for (int e = beg; e < end; ++e) {
        int2 en = g_edge[e];                           // warp-uniform broadcast
        float norm = __int_as_float(en.y);
        float2 v = g_h1[(size_t)en.x * 32 + lane];     // coalesced 256B row
        acc.x = fmaf(v.x, norm, acc.x);
        acc.y = fmaf(v.y, norm, acc.y);
    }

    float rx = fmaxf(acc.x + b1[2 * lane + 0], 0.0f);
    float ry = fmaxf(acc.y + b1[2 * lane + 1], 0.0f);

    // layer-2 GEMV partials: msg2[n] = relu_row . W2 (W2 is [HID][2])
    float a0 = rx * W2s[4 * lane + 0] + ry * W2s[4 * lane + 2];
    float a1 = rx * W2s[4 * lane + 1] + ry * W2s[4 * lane + 3];
#pragma unroll
    for (int o = 16; o > 0; o >>= 1) {
        a0 += __shfl_down_sync(0xffffffffu, a0, o);
        a1 += __shfl_down_sync(0xffffffffu, a1, o);
    }
    if (lane == 0) g_msg2[node] = make_float2(a0, a1);
}

// ---------------- K6: fused gather2 + mean-pool (one block per graph) ---------------
__device__ __forceinline__ int lower_bound_i(const int* __restrict__ a, int key) {
    int lo = 0, hi = N_NODES;
    while (lo < hi) {
        int mid = (lo + hi) >> 1;
        if (a[mid] < key) lo = mid + 1; else hi = mid;
    }
    return lo;
}

__global__ void __launch_bounds__(256) k_pool(const int* __restrict__ batch,
                                              const float* __restrict__ b2,
                                              float* __restrict__ out) {
    __shared__ float sx[256], sy[256];
    int g = blockIdx.x;
    int lo = lower_bound_i(batch, g);
    int hi = lower_bound_i(batch, g + 1);
    float bx = b2[0], by = b2[1];
    float ax = 0.0f, ay = 0.0f;
    for (int i = lo + threadIdx.x; i < hi; i += 256) {
        float dn = g_dinv[i];
        float2 m = g_msg2[i];
        float d2 = dn * dn;
        float vx = bx + m.x * d2;
        float vy = by + m.y * d2;
        int beg = g_off[i], end = g_off[i + 1];
        int e = beg;
        for (; e + 2 <= end; e += 2) {
            int2 e0 = g_edge[e];
            int2 e1 = g_edge[e + 1];
            float2 v0 = g_msg2[e0.x];
            float2 v1 = g_msg2[e1.x];
            float n0 = __int_as_float(e0.y);
            float n1 = __int_as_float(e1.y);
            vx = fmaf(v0.x, n0, vx);
            vy = fmaf(v0.y, n0, vy);
            vx = fmaf(v1.x, n1, vx);
            vy = fmaf(v1.y, n1, vy);
        }
        if (e < end) {
            int2 e0 = g_edge[e];
            float n0 = __int_as_float(e0.y);
            float2 v0 = g_msg2[e0.x];
            vx = fmaf(v0.x, n0, vx);
            vy = fmaf(v0.y, n0, vy);
        }
        ax += vx;
        ay += vy;
    }
    sx[threadIdx.x] = ax;
    sy[threadIdx.x] = ay;
    __syncthreads();
    for (int o = 128; o > 0; o >>= 1) {
        if (threadIdx.x < o) {
            sx[threadIdx.x] += sx[threadIdx.x + o];
            sy[threadIdx.x] += sy[threadIdx.x + o];
        }
        __syncthreads();
    }
    if (threadIdx.x == 0) {
        float c = fmaxf((float)(hi - lo), 1.0f);
        out[g * 2 + 0] = sx[0] / c;
        out[g * 2 + 1] = sy[0] / c;
    }
}

// ---------------- launch ----------------
// Capture order keeps k_gemm1 as the 4th kernel launch (ncu -s 5 profiles it).
extern "C" void kernel_launch(void* const* d_in, const int* in_sizes, int n_in,
                              void* d_out, int out_size) {
    const float* x     = (const float*)d_in[0];
    const int*   ei    = (const int*)d_in[1];    // int32
    const int*   batch = (const int*)d_in[2];    // int32
    const float* W1    = (const float*)d_in[3];
    const float* b1    = (const float*)d_in[4];
    const float* W2    = (const float*)d_in[5];
    const float* b2    = (const float*)d_in[6];
    float*       out   = (float*)d_out;

    cudaStream_t s2;
    cudaEvent_t evFork, evJoin;
    cudaStreamCreateWithFlags(&s2, cudaStreamNonBlocking);
    cudaEventCreateWithFlags(&evFork, cudaEventDisableTiming);
    cudaEventCreateWithFlags(&evJoin, cudaEventDisableTiming);

    // Fork point (before any main-stream work).
    cudaEventRecord(evFork, 0);
    cudaStreamWaitEvent(s2, evFork, 0);

    // Main stream: CSR build chain (indeg pre-zeroed by previous run's scatter).
    k_hist<<<(N_EDGES + 255) / 256, 256>>>(ei);        // launch 1
    k_scan1<<<NB_SCAN, 256>>>();                       // launch 2
    k_scan3<<<NB_SCAN, 256>>>();                       // launch 3

    // Side stream: dense projection (depends only on fork event).
    k_gemm1<<<(N_NODES + MT - 1) / MT, 256, 0, s2>>>(x, W1);  // launch 4 (profiled)
    cudaEventRecord(evJoin, s2);

    k_scatter<<<(N_EDGES + 255) / 256, 256>>>(ei);     // launch 5

    // Join: gather1 needs both h1 and the CSR.
    cudaStreamWaitEvent(0, evJoin, 0);
    k_gather1<<<(N_NODES + 7) / 8, 256>>>(b1, W2);     // launch 6
    k_pool<<<N_GRAPHS, 256>>>(batch, b2, out);         // launch 7
}

// round 15
// speedup vs baseline: 2.6678x; 1.0131x over previous
#include <cuda_runtime.h>
#include <cuda_fp16.h>

#define N_NODES  100000
#define N_EDGES  1600000
#define N_GRAPHS 512
#define F_IN     256
#define HID      64
#define NB_SCAN  ((N_NODES + 255) / 256)   // 391 scan blocks

typedef unsigned long long ull;

// ---------------- scratch (static device globals; no runtime alloc) ----------------
// NOTE: g_indeg relies on zero-init at module load; k_scatter re-zeroes it each run.
__device__ __half2 g_h1[(size_t)N_NODES * 32];  // x @ W1, fp16, 32 half2 per node (12.8MB)
__device__ int     g_indeg[N_NODES];
__device__ float   g_dinv[N_NODES];
__device__ int     g_off[N_NODES + 1];
__device__ int     g_cursor[N_NODES];
__device__ int     g_bsum[NB_SCAN];
__device__ int2    g_edge[N_EDGES];             // (src, norm-as-bits), bucketed by dst
__device__ float2  g_msg2[N_NODES];             // relu(agg1) @ W2

// ---------------- tf32 / mma helpers ----------------
__device__ __forceinline__ unsigned tf32cvt(float f) {
    unsigned r;
    asm("cvt.rna.tf32.f32 %0, %1;" : "=r"(r) : "f"(f));
    return r;
}
__device__ __forceinline__ void mma_tf32(float d[4],
                                         unsigned a0, unsigned a1, unsigned a2, unsigned a3,
                                         unsigned b0, unsigned b1) {
    asm volatile(
        "mma.sync.aligned.m16n8k8.row.col.f32.tf32.tf32.f32 "
        "{%0,%1,%2,%3}, {%4,%5,%6,%7}, {%8,%9}, {%0,%1,%2,%3};"
        : "+f"(d[0]), "+f"(d[1]), "+f"(d[2]), "+f"(d[3])
        : "r"(a0), "r"(a1), "r"(a2), "r"(a3), "r"(b0), "r"(b1));
}

// ---------------- K1: in-degree histogram over dst ----------------
__global__ void k_hist(const int* __restrict__ ei) {
    int e = blockIdx.x * blockDim.x + threadIdx.x;
    if (e < N_EDGES) atomicAdd(&g_indeg[ei[N_EDGES + e]], 1);
}

// ---------------- scan helpers ----------------
__device__ __forceinline__ int warp_incl_scan(int v) {
#pragma unroll
    for (int o = 1; o < 32; o <<= 1) {
        int n = __shfl_up_sync(0xffffffffu, v, o);
        if ((threadIdx.x & 31) >= o) v += n;
    }
    return v;
}

// K2a: per-block exclusive scan of indeg + fused dinv = rsqrt(indeg+1)
__global__ void k_scan1(void) {
    __shared__ int wsum[8];
    __shared__ int woff[8];
    int i = blockIdx.x * 256 + threadIdx.x;
    int v = (i < N_NODES) ? g_indeg[i] : 0;
    if (i < N_NODES) g_dinv[i] = rsqrtf((float)(v + 1));
    int incl = warp_incl_scan(v);
    int lane = threadIdx.x & 31, wid = threadIdx.x >> 5;
    if (lane == 31) wsum[wid] = incl;
    __syncthreads();
    if (threadIdx.x == 0) {
        int r = 0;
#pragma unroll
        for (int w = 0; w < 8; ++w) { woff[w] = r; r += wsum[w]; }
        g_bsum[blockIdx.x] = r;
    }
    __syncthreads();
    if (i < N_NODES) g_off[i] = incl - v + woff[wid];
}

// K2b: fused block-sum prefix + finalize offsets
__global__ void k_scan3(void) {
    __shared__ int red[256];
    int t = threadIdx.x;
    int acc = 0;
    for (int j = t; j < NB_SCAN; j += 256)
        if (j < blockIdx.x) acc += g_bsum[j];
    red[t] = acc;
    __syncthreads();
    for (int o = 128; o > 0; o >>= 1) {
        if (t < o) red[t] += red[t + o];
        __syncthreads();
    }
    int base = red[0];
    int i = blockIdx.x * 256 + t;
    if (i < N_NODES) {
        int o = g_off[i] + base;
        g_off[i] = o;
        g_cursor[i] = o;
    }
    if (i == 0) g_off[N_NODES] = N_EDGES;
}

// ---------------- K3: scatter edges into dst buckets; re-zero indeg for next run ----
__global__ void k_scatter(const int* __restrict__ ei) {
    int e = blockIdx.x * blockDim.x + threadIdx.x;
    if (e < N_NODES) g_indeg[e] = 0;   // indeg dead after scan1; reset for next replay
    if (e >= N_EDGES) return;
    int s = ei[e];
    int d = ei[N_EDGES + e];
    float norm = g_dinv[s] * g_dinv[d];
    int pos = atomicAdd(&g_cursor[d], 1);
    g_edge[pos] = make_int2(s, __float_as_int(norm));
}

// ---------------- K4: GEMM1  h1 = x @ W1  (tf32 mma.sync, fp16 epilogue) ------------
// Block: 8 warps, tile m128 x n64. Warp w: rows w*16..w*16+15, all 64 cols
// (8 n-tiles of m16n8k8). K staged in KT=32 chunks.
// xs[128][36]: A-frag bank = (4g+c)%32 -> conflict-free; 144B rows (16B aligned).
// ws[32][72]:  B-frag bank = (8c+g)%32 -> conflict-free; 288B rows (16B aligned).
#define MT 128
#define KT 32
#define XPAD 36
#define WPAD 72
__global__ void __launch_bounds__(256) k_gemm1(const float* __restrict__ x,
                                               const float* __restrict__ W1) {
    __shared__ unsigned xs[MT][XPAD];   // [node][k] tf32 bits, 18KB
    __shared__ unsigned ws[KT][WPAD];   // [k][col]  tf32 bits,  9KB
    int t = threadIdx.x;
    int w = t >> 5;                     // warp 0..7
    int lane = t & 31;
    int g = lane >> 2;                  // 0..7
    int c = lane & 3;                   // 0..3
    int mb = w * 16;
    int base = blockIdx.x * MT;

    float acc[8][4];                    // [n-tile][frag]
#pragma unroll
    for (int nt = 0; nt < 8; ++nt)
#pragma unroll
        for (int i = 0; i < 4; ++i) acc[nt][i] = 0.0f;

    for (int kt = 0; kt < F_IN; kt += KT) {
        __syncthreads();
        // load X tile: 128 nodes x 32 k (1024 float4), coalesced, tf32-converted
#pragma unroll
        for (int r = 0; r < 4; ++r) {
            int idx = t + r * 256;
            int node = idx >> 3;
            int c4 = idx & 7;
            int gn = base + node;
            float4 v = make_float4(0.f, 0.f, 0.f, 0.f);
            if (gn < N_NODES)
                v = *reinterpret_cast<const float4*>(x + (size_t)gn * F_IN + kt + c4 * 4);
            uint4 u = make_uint4(tf32cvt(v.x), tf32cvt(v.y), tf32cvt(v.z), tf32cvt(v.w));
            *reinterpret_cast<uint4*>(&xs[node][c4 * 4]) = u;
        }
        // load W tile: 32 k x 64 cols (512 float4)
#pragma unroll
        for (int r = 0; r < 2; ++r) {
            int idx = t + r * 256;
            int row = idx >> 4;
            int c4 = idx & 15;
            float4 v = *reinterpret_cast<const float4*>(W1 + (size_t)(kt + row) * HID + c4 * 4);
            uint4 u = make_uint4(tf32cvt(v.x), tf32cvt(v.y), tf32cvt(v.z), tf32cvt(v.w));
            *reinterpret_cast<uint4*>(&ws[row][c4 * 4]) = u;
        }
        __syncthreads();

#pragma unroll
        for (int k8 = 0; k8 < KT; k8 += 8) {
            unsigned a0 = xs[mb + g][k8 + c];
            unsigned a1 = xs[mb + g + 8][k8 + c];
            unsigned a2 = xs[mb + g][k8 + c + 4];
            unsigned a3 = xs[mb + g + 8][k8 + c + 4];
#pragma unroll
            for (int nt = 0; nt < 8; ++nt) {
                unsigned b0 = ws[k8 + c][nt * 8 + g];
                unsigned b1 = ws[k8 + c + 4][nt * 8 + g];
                mma_tf32(acc[nt], a0, a1, a2, a3, b0, b1);
            }
        }
    }

    // store fp16: thread owns rows (mb+g, mb+g+8), cols nt*8 + c*2 (+1)
    int gn0 = base + mb + g;
    int gn1 = gn0 + 8;
#pragma unroll
    for (int nt = 0; nt < 8; ++nt) {
        int f2 = nt * 4 + c;            // half2 index within the 32-half2 row
        if (gn0 < N_NODES) g_h1[(size_t)gn0 * 32 + f2] = __floats2half2_rn(acc[nt][0], acc[nt][1]);
        if (gn1 < N_NODES) g_h1[(size_t)gn1 * 32 + f2] = __floats2half2_rn(acc[nt][2], acc[nt][3]);
    }
}

// ---------------- K5: fused gather1 + bias + relu + layer2 GEMV ----------------
// One warp per node; lane owns columns [2*lane, 2*lane+1]. h1 rows are 128B fp16.
__global__ void __launch_bounds__(256) k_gather1(const float* __restrict__ b1,
                                                 const float* __restrict__ W2) {
    __shared__ float W2s[HID * 2];
    if (threadIdx.x < HID * 2) W2s[threadIdx.x] = W2[threadIdx.x];
    __syncthreads();

    int node = blockIdx.x * 8 + (threadIdx.x >> 5);
    if (node >= N_NODES) return;
    int lane = threadIdx.x & 31;

    float dn = g_dinv[node];

    // self loop: dinv[n]^2 * h1[n]
    float2 hv = __half22float2(g_h1[(size_t)node * 32 + lane]);
    float d2 = dn * dn;
    float2 acc = make_float2(hv.x * d2, hv.y * d2);

    int beg = g_off[node], end = g_off[node + 1];
    for (int e = beg; e < end; ++e) {
        int2 en = g_edge[e];                                       // warp-uniform
        float norm = __int_as_float(en.y);
        float2 v = __half22float2(g_h1[(size_t)en.x * 32 + lane]); // coalesced 128B row
        acc.x = fmaf(v.x, norm, acc.x);
        acc.y = fmaf(v.y, norm, acc.y);
    }

    float rx = fmaxf(acc.x + b1[2 * lane + 0], 0.0f);
    float ry = fmaxf(acc.y + b1[2 * lane + 1], 0.0f);

    // layer-2 GEMV partials: msg2[n] = relu_row . W2 (W2 is [HID][2])
    float a0 = rx * W2s[4 * lane + 0] + ry * W2s[4 * lane + 2];
    float a1 = rx * W2s[4 * lane + 1] + ry * W2s[4 * lane + 3];
#pragma unroll
    for (int o = 16; o > 0; o >>= 1) {
        a0 += __shfl_down_sync(0xffffffffu, a0, o);
        a1 += __shfl_down_sync(0xffffffffu, a1, o);
    }
    if (lane == 0) g_msg2[node] = make_float2(a0, a1);
}

// ---------------- K6: fused gather2 + mean-pool (one block per graph) ---------------
__device__ __forceinline__ int lower_bound_i(const int* __restrict__ a, int key) {
    int lo = 0, hi = N_NODES;
    while (lo < hi) {
        int mid = (lo + hi) >> 1;
        if (a[mid] < key) lo = mid + 1; else hi = mid;
    }
    return lo;
}

__global__ void __launch_bounds__(256) k_pool(const int* __restrict__ batch,
                                              const float* __restrict__ b2,
                                              float* __restrict__ out) {
    __shared__ float sx[256], sy[256];
    int g = blockIdx.x;
    int lo = lower_bound_i(batch, g);
    int hi = lower_bound_i(batch, g + 1);
    float bx = b2[0], by = b2[1];
    float ax = 0.0f, ay = 0.0f;
    for (int i = lo + threadIdx.x; i < hi; i += 256) {
        float dn = g_dinv[i];
        float2 m = g_msg2[i];
        float d2 = dn * dn;
        float vx = bx + m.x * d2;
        float vy = by + m.y * d2;
        int beg = g_off[i], end = g_off[i + 1];
        int e = beg;
        for (; e + 2 <= end; e += 2) {
            int2 e0 = g_edge[e];
            int2 e1 = g_edge[e + 1];
            float2 v0 = g_msg2[e0.x];
            float2 v1 = g_msg2[e1.x];
            float n0 = __int_as_float(e0.y);
            float n1 = __int_as_float(e1.y);
            vx = fmaf(v0.x, n0, vx);
            vy = fmaf(v0.y, n0, vy);
            vx = fmaf(v1.x, n1, vx);
            vy = fmaf(v1.y, n1, vy);
        }
        if (e < end) {
            int2 e0 = g_edge[e];
            float n0 = __int_as_float(e0.y);
            float2 v0 = g_msg2[e0.x];
            vx = fmaf(v0.x, n0, vx);
            vy = fmaf(v0.y, n0, vy);
        }
        ax += vx;
        ay += vy;
    }
    sx[threadIdx.x] = ax;
    sy[threadIdx.x] = ay;
    __syncthreads();
    for (int o = 128; o > 0; o >>= 1) {
        if (threadIdx.x < o) {
            sx[threadIdx.x] += sx[threadIdx.x + o];
            sy[threadIdx.x] += sy[threadIdx.x + o];
        }
        __syncthreads();
    }
    if (threadIdx.x == 0) {
        float c = fmaxf((float)(hi - lo), 1.0f);
        out[g * 2 + 0] = sx[0] / c;
        out[g * 2 + 1] = sy[0] / c;
    }
}

// ---------------- launch ----------------
// Capture order keeps k_gemm1 as the 4th kernel launch (ncu -s 5 profiles it).
extern "C" void kernel_launch(void* const* d_in, const int* in_sizes, int n_in,
                              void* d_out, int out_size) {
    const float* x     = (const float*)d_in[0];
    const int*   ei    = (const int*)d_in[1];    // int32
    const int*   batch = (const int*)d_in[2];    // int32
    const float* W1    = (const float*)d_in[3];
    const float* b1    = (const float*)d_in[4];
    const float* W2    = (const float*)d_in[5];
    const float* b2    = (const float*)d_in[6];
    float*       out   = (float*)d_out;

    cudaStream_t s2;
    cudaEvent_t evFork, evJoin;
    cudaStreamCreateWithFlags(&s2, cudaStreamNonBlocking);
    cudaEventCreateWithFlags(&evFork, cudaEventDisableTiming);
    cudaEventCreateWithFlags(&evJoin, cudaEventDisableTiming);

    // Fork point (before any main-stream work).
    cudaEventRecord(evFork, 0);
    cudaStreamWaitEvent(s2, evFork, 0);

    // Main stream: CSR build chain (indeg pre-zeroed by previous run's scatter).
    k_hist<<<(N_EDGES + 255) / 256, 256>>>(ei);        // launch 1
    k_scan1<<<NB_SCAN, 256>>>();                       // launch 2
    k_scan3<<<NB_SCAN, 256>>>();                       // launch 3

    // Side stream: dense projection (depends only on fork event).
    k_gemm1<<<(N_NODES + MT - 1) / MT, 256, 0, s2>>>(x, W1);  // launch 4 (profiled)
    cudaEventRecord(evJoin, s2);

    k_scatter<<<(N_EDGES + 255) / 256, 256>>>(ei);     // launch 5

    // Join: gather1 needs both h1 and the CSR.
    cudaStreamWaitEvent(0, evJoin, 0);
    k_gather1<<<(N_NODES + 7) / 8, 256>>>(b1, W2);     // launch 6
    k_pool<<<N_GRAPHS, 256>>>(batch, b2, out);         // launch 7
}